// round 9
// baseline (speedup 1.0000x reference)
#include <cuda_runtime.h>
#include <cuda_bf16.h>
#include <math.h>
#include <cstdint>

#define N_NODES 100000
#define N_EDGES 3200000
#define F_IN    512
#define F_H     256
#define F_OUT   64

// ---------------- scratch (device globals: no alloc allowed) ----------------
__device__ int   g_deg[N_NODES];
__device__ int   g_cursor[N_NODES];
__device__ int   g_rowptr[N_NODES + 1];
__device__ float g_dis[N_NODES];
__device__ int   g_csr[N_EDGES];
__device__ float g_csrw[N_EDGES];       // per-edge weight dis[src]
__device__ int   g_blksum[128];
__device__ int   g_blkoff[128];
__device__ __nv_bfloat16 g_ahi[(size_t)N_NODES * F_IN];   // activation hi plane
__device__ __nv_bfloat16 g_alo[(size_t)N_NODES * F_IN];   // activation lo plane
__device__ float g_goutA[(size_t)N_NODES * F_H];          // GEMM output buffer A
__device__ float g_goutB[(size_t)N_NODES * F_H];          // GEMM output buffer B
__device__ __nv_bfloat16 g_whi[4][(size_t)F_IN * F_H];    // W^T hi plane [N][K]
__device__ __nv_bfloat16 g_wlo[4][(size_t)F_IN * F_H];    // W^T lo plane [N][K]

// ---------------- packing helpers ----------------
__device__ __forceinline__ void split_bf16(float v, __nv_bfloat16& hi, __nv_bfloat16& lo) {
    hi = __float2bfloat16(v);
    lo = __float2bfloat16(v - __bfloat162float(hi));
}

__global__ void pack_x_kernel(const float* __restrict__ x,
                              __nv_bfloat16* __restrict__ hi,
                              __nv_bfloat16* __restrict__ lo, int n4) {
    int i = blockIdx.x * blockDim.x + threadIdx.x;
    if (i < n4) {
        float4 v = *(const float4*)(x + (size_t)i * 4);
        __nv_bfloat16 h0, l0, h1, l1, h2, l2, h3, l3;
        split_bf16(v.x, h0, l0); split_bf16(v.y, h1, l1);
        split_bf16(v.z, h2, l2); split_bf16(v.w, h3, l3);
        __nv_bfloat162 hh0 = __halves2bfloat162(h0, h1);
        __nv_bfloat162 hh1 = __halves2bfloat162(h2, h3);
        __nv_bfloat162 ll0 = __halves2bfloat162(l0, l1);
        __nv_bfloat162 ll1 = __halves2bfloat162(l2, l3);
        *(uint2*)(hi + (size_t)i * 4) = make_uint2(*(uint32_t*)&hh0, *(uint32_t*)&hh1);
        *(uint2*)(lo + (size_t)i * 4) = make_uint2(*(uint32_t*)&ll0, *(uint32_t*)&ll1);
    }
}

// W [K,N] fp32 -> W^T planes [N][K]
__global__ void pack_w_kernel(const float* __restrict__ W,
                              __nv_bfloat16* __restrict__ hi,
                              __nv_bfloat16* __restrict__ lo, int K, int N) {
    int i = blockIdx.x * blockDim.x + threadIdx.x;
    if (i < K * N) {
        int k = i / N, n = i % N;
        __nv_bfloat16 h, l;
        split_bf16(W[i], h, l);
        hi[(size_t)n * K + k] = h;
        lo[(size_t)n * K + k] = l;
    }
}

// ---------------- CSR build ----------------
__global__ void zero_kernel() {
    int i = blockIdx.x * blockDim.x + threadIdx.x;
    if (i < N_NODES) { g_deg[i] = 0; g_cursor[i] = 0; }
}
__global__ void count_kernel(const int* __restrict__ ei) {
    int e = blockIdx.x * blockDim.x + threadIdx.x;
    if (e < N_EDGES) atomicAdd(&g_deg[ei[N_EDGES + e]], 1);
}
__global__ void dis_kernel() {
    int n = blockIdx.x * blockDim.x + threadIdx.x;
    if (n < N_NODES) g_dis[n] = rsqrtf((float)g_deg[n] + 1.0f);
}
__global__ void scan1_kernel() {
    __shared__ int sh[1024];
    int tid = threadIdx.x;
    int idx = blockIdx.x * 1024 + tid;
    int v = (idx < N_NODES) ? g_deg[idx] : 0;
    sh[tid] = v;
    __syncthreads();
    #pragma unroll
    for (int off = 1; off < 1024; off <<= 1) {
        int t = (tid >= off) ? sh[tid - off] : 0;
        __syncthreads();
        sh[tid] += t;
        __syncthreads();
    }
    if (idx < N_NODES) g_rowptr[idx] = sh[tid] - v;
    if (tid == 1023) g_blksum[blockIdx.x] = sh[1023];
}
__global__ void scan2_kernel(int nblk) {
    if (threadIdx.x == 0) {
        int run = 0;
        for (int b = 0; b < nblk; b++) { int t = g_blksum[b]; g_blkoff[b] = run; run += t; }
        g_rowptr[N_NODES] = run;
    }
}
__global__ void scan3_kernel() {
    int idx = blockIdx.x * 1024 + threadIdx.x;
    if (idx < N_NODES) g_rowptr[idx] += g_blkoff[blockIdx.x];
}
__global__ void scatter_kernel(const int* __restrict__ ei) {
    int e = blockIdx.x * blockDim.x + threadIdx.x;
    if (e < N_EDGES) {
        int d = ei[N_EDGES + e];
        int s = ei[e];
        int pos = atomicAdd(&g_cursor[d], 1);
        int slot = g_rowptr[d] + pos;
        g_csr[slot] = s;
        g_csrw[slot] = g_dis[s];
    }
}

// ---------------- mma.sync bf16 GEMM: C[M,N] = A[M,K] @ W[K,N] (W^T planes given) ----------------
// fp32 emulation: C = Ah*Bh + Al*Bh + Ah*Bl. BM=128, BN template, BK=32.
// 8 warps: 4 in M x 2 in N. cp.async double-buffered; ldmatrix.x4 fragments.
// B hi/lo fragments share registers (two phases per k-step) -> <=128 regs -> 2 CTAs/SM.
__device__ __forceinline__ void cp_async16(uint32_t dst, const void* src, int szr) {
    asm volatile("cp.async.ca.shared.global [%0], [%1], 16, %2;"
                 :: "r"(dst), "l"(src), "r"(szr));
}
__device__ __forceinline__ void mma16816(float* c, const uint32_t* a, const uint32_t* b) {
    asm volatile(
        "mma.sync.aligned.m16n8k16.row.col.f32.bf16.bf16.f32 "
        "{%0,%1,%2,%3}, {%4,%5,%6,%7}, {%8,%9}, {%0,%1,%2,%3};"
        : "+f"(c[0]), "+f"(c[1]), "+f"(c[2]), "+f"(c[3])
        : "r"(a[0]), "r"(a[1]), "r"(a[2]), "r"(a[3]), "r"(b[0]), "r"(b[1]));
}
__device__ __forceinline__ void ldsm_x4(uint32_t* r, uint32_t addr) {
    asm volatile("ldmatrix.sync.aligned.m8n8.x4.shared.b16 {%0,%1,%2,%3}, [%4];"
        : "=r"(r[0]), "=r"(r[1]), "=r"(r[2]), "=r"(r[3]) : "r"(addr));
}

template<int BN>
__global__ void __launch_bounds__(256, 2)
mma_gemm_kernel(const __nv_bfloat16* __restrict__ Ahi, const __nv_bfloat16* __restrict__ Alo,
                const __nv_bfloat16* __restrict__ Bhi, const __nv_bfloat16* __restrict__ Blo,
                float* __restrict__ C, int M, int N, int K, int ty0) {
    extern __shared__ char smem[];
    const int BSZ = BN * 80;
    const int BUF = 20480 + 2 * BSZ;
    const int NT = BN / 16;
    uint32_t sbase;
    asm("{ .reg .u64 t; cvta.to.shared.u64 t, %1; cvt.u32.u64 %0, t; }"
        : "=r"(sbase) : "l"(smem));

    int tid = threadIdx.x, lane = tid & 31, wid = tid >> 5;
    int gID = lane >> 2, tig = lane & 3;
    int warpM = (wid & 3) * 32, warpN = (wid >> 2) * (BN / 2);
    int bm = (ty0 + blockIdx.y) * 128, bn = blockIdx.x * BN;

    uint32_t aOff = (uint32_t)((warpM + (lane & 7) + ((lane >> 3) & 1) * 8) * 80
                               + (lane >> 4) * 16);
    uint32_t b4Off = (uint32_t)((warpN + ((lane >> 4) << 3) + (lane & 7)) * 80
                                + ((lane >> 3) & 1) * 16);

    float acc[2][NT][4];
    #pragma unroll
    for (int i = 0; i < 2; i++)
        #pragma unroll
        for (int j = 0; j < NT; j++)
            #pragma unroll
            for (int q = 0; q < 4; q++) acc[i][j][q] = 0.f;

    int nch = K >> 5;

    auto load_tile = [&](int buf, int c) {
        uint32_t bb = sbase + buf * BUF;
        #pragma unroll
        for (int it = 0; it < 4; it++) {
            int idx = tid + it * 256;
            int ch = idx & 3, r = (idx >> 2) & 127, pl = idx >> 9;
            int row = bm + r;
            int szr = (row < M) ? 16 : 0;
            int rowc = (row < M) ? row : (M - 1);
            const __nv_bfloat16* src = (pl ? Alo : Ahi) + (size_t)rowc * K + c * 32 + ch * 8;
            cp_async16(bb + pl * 10240 + r * 80 + ch * 16, src, szr);
        }
        #pragma unroll
        for (int it = 0; it < BN / 32; it++) {
            int idx = tid + it * 256;
            int ch = idx & 3, r = (idx >> 2) % BN, pl = idx / (BN * 4);
            const __nv_bfloat16* src = (pl ? Blo : Bhi) + (size_t)(bn + r) * K + c * 32 + ch * 8;
            cp_async16(bb + 20480 + pl * BSZ + r * 80 + ch * 16, src, 16);
        }
    };

    load_tile(0, 0);
    asm volatile("cp.async.commit_group;");

    for (int c = 0; c < nch; c++) {
        if (c + 1 < nch) load_tile((c + 1) & 1, c + 1);
        asm volatile("cp.async.commit_group;");
        asm volatile("cp.async.wait_group 1;");
        __syncthreads();

        uint32_t bufb = sbase + (c & 1) * BUF;
        uint32_t aHi = bufb + aOff;
        uint32_t aLo = aHi + 10240;
        uint32_t bHi = bufb + 20480 + b4Off;
        uint32_t bLo = bHi + BSZ;

        #pragma unroll
        for (int ks = 0; ks < 2; ks++) {
            uint32_t ah[2][4], al[2][4], bb2[NT][2];
            #pragma unroll
            for (int mt = 0; mt < 2; mt++) {
                ldsm_x4(ah[mt], aHi + mt * (16 * 80) + ks * 32);
                ldsm_x4(al[mt], aLo + mt * (16 * 80) + ks * 32);
            }
            #pragma unroll
            for (int p = 0; p < NT / 2; p++)
                ldsm_x4(&bb2[2 * p][0], bHi + p * (16 * 80) + ks * 32);
            #pragma unroll
            for (int mt = 0; mt < 2; mt++)
                #pragma unroll
                for (int nt = 0; nt < NT; nt++) {
                    mma16816(acc[mt][nt], ah[mt], bb2[nt]);
                    mma16816(acc[mt][nt], al[mt], bb2[nt]);
                }
            #pragma unroll
            for (int p = 0; p < NT / 2; p++)
                ldsm_x4(&bb2[2 * p][0], bLo + p * (16 * 80) + ks * 32);
            #pragma unroll
            for (int mt = 0; mt < 2; mt++)
                #pragma unroll
                for (int nt = 0; nt < NT; nt++)
                    mma16816(acc[mt][nt], ah[mt], bb2[nt]);
        }
        __syncthreads();
    }

    #pragma unroll
    for (int mt = 0; mt < 2; mt++) {
        int row0 = bm + warpM + mt * 16 + gID;
        #pragma unroll
        for (int nt = 0; nt < NT; nt++) {
            int col = bn + warpN + nt * 8 + tig * 2;
            if (row0 < M)
                *(float2*)(C + (size_t)row0 * N + col) = make_float2(acc[mt][nt][0], acc[mt][nt][1]);
            if (row0 + 8 < M)
                *(float2*)(C + (size_t)(row0 + 8) * N + col) = make_float2(acc[mt][nt][2], acc[mt][nt][3]);
        }
    }
}

// ---------------- aggregation: float4 gather, 4 nodes per 256-thread block, node range [n0,n1) ----------------
__global__ void __launch_bounds__(256)
agg_pack_kernel(const float* __restrict__ h,
                const float* __restrict__ bias,
                __nv_bfloat16* __restrict__ ohi,
                __nv_bfloat16* __restrict__ olo, int n0, int n1) {
    __shared__ int   sE[4][64];
    __shared__ float sW[4][64];
    int g = threadIdx.x >> 6;
    int t = threadIdx.x & 63;
    int node = n0 + blockIdx.x * 4 + g;
    bool valid = node < n1;

    int beg = 0, end = 0;
    if (valid) { beg = g_rowptr[node]; end = g_rowptr[node + 1]; }
    float4 acc = make_float4(0.f, 0.f, 0.f, 0.f);

    for (int cs = beg; cs < end; cs += 64) {
        int cnt = min(64, end - cs);
        if (t < cnt) { sE[g][t] = g_csr[cs + t]; sW[g][t] = g_csrw[cs + t]; }
        __syncthreads();
        #pragma unroll 2
        for (int i = 0; i < cnt; i++) {
            float w = sW[g][i];
            float4 v = __ldg((const float4*)(h + (size_t)sE[g][i] * F_H + t * 4));
            acc.x = fmaf(w, v.x, acc.x); acc.y = fmaf(w, v.y, acc.y);
            acc.z = fmaf(w, v.z, acc.z); acc.w = fmaf(w, v.w, acc.w);
        }
        __syncthreads();
    }
    if (valid) {
        float dn = g_dis[node];
        float4 hv = *(const float4*)(h + (size_t)node * F_H + t * 4);
        const float4 bv = *(const float4*)(bias + t * 4);
        float r[4] = {
            dn * fmaf(dn, hv.x, acc.x) + bv.x,
            dn * fmaf(dn, hv.y, acc.y) + bv.y,
            dn * fmaf(dn, hv.z, acc.z) + bv.z,
            dn * fmaf(dn, hv.w, acc.w) + bv.w };
        __nv_bfloat16 hi[4], lo[4];
        #pragma unroll
        for (int q = 0; q < 4; q++) {
            float v = r[q] > 0.f ? r[q] : 0.01f * r[q];
            split_bf16(v, hi[q], lo[q]);
        }
        __nv_bfloat162 hh0 = __halves2bfloat162(hi[0], hi[1]);
        __nv_bfloat162 hh1 = __halves2bfloat162(hi[2], hi[3]);
        __nv_bfloat162 ll0 = __halves2bfloat162(lo[0], lo[1]);
        __nv_bfloat162 ll1 = __halves2bfloat162(lo[2], lo[3]);
        *(uint2*)(ohi + (size_t)node * F_H + t * 4) = make_uint2(*(uint32_t*)&hh0, *(uint32_t*)&hh1);
        *(uint2*)(olo + (size_t)node * F_H + t * 4) = make_uint2(*(uint32_t*)&ll0, *(uint32_t*)&ll1);
    }
}

// last layer: agg (F=64) + bias + softmax. 16 threads x float4 per node, 16 nodes per block.
__global__ void __launch_bounds__(256)
agg_softmax_kernel(const float* __restrict__ h,
                   const float* __restrict__ bias,
                   float* __restrict__ out) {
    int g = threadIdx.x >> 4;
    int t = threadIdx.x & 15;
    int node = blockIdx.x * 16 + g;
    bool valid = node < N_NODES;

    float4 acc = make_float4(0.f, 0.f, 0.f, 0.f);
    if (valid) {
        int beg = g_rowptr[node], end = g_rowptr[node + 1];
        for (int e = beg; e < end; e++) {
            float w = g_csrw[e];
            float4 v = __ldg((const float4*)(h + (size_t)g_csr[e] * 64 + t * 4));
            acc.x = fmaf(w, v.x, acc.x); acc.y = fmaf(w, v.y, acc.y);
            acc.z = fmaf(w, v.z, acc.z); acc.w = fmaf(w, v.w, acc.w);
        }
        float dn = g_dis[node];
        float4 hv = *(const float4*)(h + (size_t)node * 64 + t * 4);
        const float4 bv = *(const float4*)(bias + t * 4);
        acc.x = dn * fmaf(dn, hv.x, acc.x) + bv.x;
        acc.y = dn * fmaf(dn, hv.y, acc.y) + bv.y;
        acc.z = dn * fmaf(dn, hv.z, acc.z) + bv.z;
        acc.w = dn * fmaf(dn, hv.w, acc.w) + bv.w;
    }
    float m = fmaxf(fmaxf(acc.x, acc.y), fmaxf(acc.z, acc.w));
    #pragma unroll
    for (int off = 8; off > 0; off >>= 1)
        m = fmaxf(m, __shfl_xor_sync(0xffffffffu, m, off, 16));
    float ex = expf(acc.x - m), ey = expf(acc.y - m);
    float ez = expf(acc.z - m), ew = expf(acc.w - m);
    float s = ex + ey + ez + ew;
    #pragma unroll
    for (int off = 8; off > 0; off >>= 1)
        s += __shfl_xor_sync(0xffffffffu, s, off, 16);
    if (valid) {
        float inv = 1.f / s;
        *(float4*)(out + (size_t)node * 64 + t * 4) = make_float4(ex * inv, ey * inv, ez * inv, ew * inv);
    }
}

// ---------------- launch ----------------
extern "C" void kernel_launch(void* const* d_in, const int* in_sizes, int n_in,
                              void* d_out, int out_size) {
    const float* x  = (const float*)d_in[0];
    const int*   ei = (const int*)  d_in[1];
    const float* W0 = (const float*)d_in[2];
    const float* b0 = (const float*)d_in[3];
    const float* W1 = (const float*)d_in[4];
    const float* b1 = (const float*)d_in[5];
    const float* W2 = (const float*)d_in[6];
    const float* b2 = (const float*)d_in[7];
    const float* W3 = (const float*)d_in[8];
    const float* b3 = (const float*)d_in[9];
    float* out = (float*)d_out;

    __nv_bfloat16 *ahi, *alo, *whibase, *wlobase;
    float *goutA, *goutB;
    cudaGetSymbolAddress((void**)&ahi, g_ahi);
    cudaGetSymbolAddress((void**)&alo, g_alo);
    cudaGetSymbolAddress((void**)&whibase, g_whi);
    cudaGetSymbolAddress((void**)&wlobase, g_wlo);
    cudaGetSymbolAddress((void**)&goutA, g_goutA);
    cudaGetSymbolAddress((void**)&goutB, g_goutB);
    const size_t WSTRIDE = (size_t)F_IN * F_H;

    const int SM128 = 20480 + 2 * 128 * 80;          // per buffer
    const int SM64  = 20480 + 2 * 64 * 80;
    cudaFuncSetAttribute(mma_gemm_kernel<128>, cudaFuncAttributeMaxDynamicSharedMemorySize, 2 * SM128);
    cudaFuncSetAttribute(mma_gemm_kernel<64>,  cudaFuncAttributeMaxDynamicSharedMemorySize, 2 * SM64);

    // capture-safe fork/join resources (created once; reused every call)
    static cudaStream_t s2 = []{
        cudaStream_t s; cudaStreamCreateWithFlags(&s, cudaStreamNonBlocking); return s; }();
    static cudaEvent_t evFork = []{
        cudaEvent_t e; cudaEventCreateWithFlags(&e, cudaEventDisableTiming); return e; }();
    static cudaEvent_t evJoin = []{
        cudaEvent_t e; cudaEventCreateWithFlags(&e, cudaEventDisableTiming); return e; }();
    static cudaEvent_t eA[3][4];
    static cudaEvent_t eG[3];
    static bool evInit = []{
        for (int i = 0; i < 3; i++) {
            cudaEventCreateWithFlags(&eG[i], cudaEventDisableTiming);
            for (int j = 0; j < 4; j++)
                cudaEventCreateWithFlags(&eA[i][j], cudaEventDisableTiming);
        }
        return true; }();
    (void)evInit;

    const int TB = 256;
    int nblk_nodes = (N_NODES + TB - 1) / TB;
    int nblk_edges = (N_EDGES + TB - 1) / TB;
    int scan_blks = (N_NODES + 1023) / 1024;
    int mtiles = (N_NODES + 127) / 128;             // 782

    // chunk boundaries (tile-aligned quarters)
    static const int qt[5] = {0, 196, 392, 588, 782};

    // fork: CSR build on s2, concurrent with packing + gemm0 on main stream
    cudaEventRecord(evFork, 0);
    cudaStreamWaitEvent(s2, evFork, 0);

    zero_kernel<<<nblk_nodes, TB, 0, s2>>>();
    count_kernel<<<nblk_edges, TB, 0, s2>>>(ei);
    dis_kernel<<<nblk_nodes, TB, 0, s2>>>();
    scan1_kernel<<<scan_blks, 1024, 0, s2>>>();
    scan2_kernel<<<1, 32, 0, s2>>>(scan_blks);
    scan3_kernel<<<scan_blks, 1024, 0, s2>>>();
    scatter_kernel<<<nblk_edges, TB, 0, s2>>>(ei);
    cudaEventRecord(evJoin, s2);

    // main stream: packs + gemm0 (full)
    pack_x_kernel<<<(N_NODES * F_IN / 4 + TB - 1) / TB, TB>>>(x, ahi, alo, N_NODES * F_IN / 4);
    pack_w_kernel<<<(F_IN * F_H + TB - 1) / TB, TB>>>(W0, whibase, wlobase, F_IN, F_H);
    pack_w_kernel<<<(F_H * F_H + TB - 1) / TB, TB>>>(W1, whibase + WSTRIDE, wlobase + WSTRIDE, F_H, F_H);
    mma_gemm_kernel<128><<<dim3(2, mtiles), TB, 2 * SM128>>>(ahi, alo, whibase, wlobase, goutA,
                                                             N_NODES, F_H, F_IN, 0);
    pack_w_kernel<<<(F_H * F_H + TB - 1) / TB, TB>>>(W2, whibase + 2 * WSTRIDE, wlobase + 2 * WSTRIDE, F_H, F_H);
    pack_w_kernel<<<(F_H * F_OUT + TB - 1) / TB, TB>>>(W3, whibase + 3 * WSTRIDE, wlobase + 3 * WSTRIDE, F_H, F_OUT);

    // join: aggregation needs the CSR
    cudaStreamWaitEvent(0, evJoin, 0);

    // pipelined layers: agg_i chunks on main; gemm_{i+1} chunks on s2 gated per-chunk
    const float* gin[4]  = {goutA, goutB, goutA, goutB};
    const float* biases[3] = {b0, b1, b2};
    const __nv_bfloat16* wh[3] = {whibase + WSTRIDE, whibase + 2 * WSTRIDE, whibase + 3 * WSTRIDE};
    const __nv_bfloat16* wl[3] = {wlobase + WSTRIDE, wlobase + 2 * WSTRIDE, wlobase + 3 * WSTRIDE};

    for (int L = 0; L < 3; L++) {
        // agg chunks on main
        for (int j = 0; j < 4; j++) {
            int n0 = qt[j] * 128;
            int n1 = min(qt[j + 1] * 128, N_NODES);
            int cnt = n1 - n0;
            agg_pack_kernel<<<(cnt + 3) / 4, TB>>>(gin[L], biases[L], ahi, alo, n0, n1);
            cudaEventRecord(eA[L][j], 0);
        }
        // gemm L+1 chunks on s2
        for (int j = 0; j < 4; j++) {
            cudaStreamWaitEvent(s2, eA[L][j], 0);
            int gy = qt[j + 1] - qt[j];
            if (L < 2) {
                mma_gemm_kernel<128><<<dim3(2, gy), TB, 2 * SM128, s2>>>(
                    ahi, alo, wh[L], wl[L], (float*)gin[L + 1], N_NODES, F_H, F_H, qt[j]);
            } else {
                mma_gemm_kernel<64><<<dim3(1, gy), TB, 2 * SM64, s2>>>(
                    ahi, alo, wh[L], wl[L], (float*)gin[L + 1], N_NODES, F_OUT, F_H, qt[j]);
            }
        }
        cudaEventRecord(eG[L], s2);
        cudaStreamWaitEvent(0, eG[L], 0);
    }

    agg_softmax_kernel<<<(N_NODES + 15) / 16, TB>>>(gin[3], b3, out);
}

// round 10
// speedup vs baseline: 1.0540x; 1.0540x over previous
#include <cuda_runtime.h>
#include <cuda_bf16.h>
#include <math.h>
#include <cstdint>

#define N_NODES 100000
#define N_EDGES 3200000
#define F_IN    512
#define F_H     256
#define F_OUT   64

// ---------------- scratch (device globals: no alloc allowed) ----------------
__device__ int   g_deg[N_NODES];
__device__ int   g_cursor[N_NODES];
__device__ int   g_rowptr[N_NODES + 1];
__device__ float g_dis[N_NODES];
__device__ int   g_csr[N_EDGES];
__device__ float g_csrw[N_EDGES];       // per-edge weight dis[src]
__device__ int   g_blksum[128];
__device__ int   g_blkoff[128];
__device__ __nv_bfloat16 g_ahi[(size_t)N_NODES * F_IN];   // activation hi plane
__device__ __nv_bfloat16 g_alo[(size_t)N_NODES * F_IN];   // activation lo plane
__device__ float g_gout[(size_t)N_NODES * F_H];           // GEMM output (pre-agg) fp32
__device__ __nv_bfloat16 g_whi[4][(size_t)F_IN * F_H];    // W^T hi plane [N][K]
__device__ __nv_bfloat16 g_wlo[4][(size_t)F_IN * F_H];    // W^T lo plane [N][K]

// ---------------- packing helpers ----------------
__device__ __forceinline__ void split_bf16(float v, __nv_bfloat16& hi, __nv_bfloat16& lo) {
    hi = __float2bfloat16(v);
    lo = __float2bfloat16(v - __bfloat162float(hi));
}

__global__ void pack_x_kernel(const float* __restrict__ x,
                              __nv_bfloat16* __restrict__ hi,
                              __nv_bfloat16* __restrict__ lo, int n4) {
    int i = blockIdx.x * blockDim.x + threadIdx.x;
    if (i < n4) {
        float4 v = *(const float4*)(x + (size_t)i * 4);
        __nv_bfloat16 h0, l0, h1, l1, h2, l2, h3, l3;
        split_bf16(v.x, h0, l0); split_bf16(v.y, h1, l1);
        split_bf16(v.z, h2, l2); split_bf16(v.w, h3, l3);
        __nv_bfloat162 hh0 = __halves2bfloat162(h0, h1);
        __nv_bfloat162 hh1 = __halves2bfloat162(h2, h3);
        __nv_bfloat162 ll0 = __halves2bfloat162(l0, l1);
        __nv_bfloat162 ll1 = __halves2bfloat162(l2, l3);
        *(uint2*)(hi + (size_t)i * 4) = make_uint2(*(uint32_t*)&hh0, *(uint32_t*)&hh1);
        *(uint2*)(lo + (size_t)i * 4) = make_uint2(*(uint32_t*)&ll0, *(uint32_t*)&ll1);
    }
}

// W [K,N] fp32 -> W^T planes [N][K]
__global__ void pack_w_kernel(const float* __restrict__ W,
                              __nv_bfloat16* __restrict__ hi,
                              __nv_bfloat16* __restrict__ lo, int K, int N) {
    int i = blockIdx.x * blockDim.x + threadIdx.x;
    if (i < K * N) {
        int k = i / N, n = i % N;
        __nv_bfloat16 h, l;
        split_bf16(W[i], h, l);
        hi[(size_t)n * K + k] = h;
        lo[(size_t)n * K + k] = l;
    }
}

// ---------------- CSR build ----------------
__global__ void zero_kernel() {
    int i = blockIdx.x * blockDim.x + threadIdx.x;
    if (i < N_NODES) { g_deg[i] = 0; g_cursor[i] = 0; }
}
__global__ void count_kernel(const int* __restrict__ ei) {
    int e = blockIdx.x * blockDim.x + threadIdx.x;
    if (e < N_EDGES) atomicAdd(&g_deg[ei[N_EDGES + e]], 1);
}
__global__ void dis_kernel() {
    int n = blockIdx.x * blockDim.x + threadIdx.x;
    if (n < N_NODES) g_dis[n] = rsqrtf((float)g_deg[n] + 1.0f);
}
__global__ void scan1_kernel() {
    __shared__ int sh[1024];
    int tid = threadIdx.x;
    int idx = blockIdx.x * 1024 + tid;
    int v = (idx < N_NODES) ? g_deg[idx] : 0;
    sh[tid] = v;
    __syncthreads();
    #pragma unroll
    for (int off = 1; off < 1024; off <<= 1) {
        int t = (tid >= off) ? sh[tid - off] : 0;
        __syncthreads();
        sh[tid] += t;
        __syncthreads();
    }
    if (idx < N_NODES) g_rowptr[idx] = sh[tid] - v;
    if (tid == 1023) g_blksum[blockIdx.x] = sh[1023];
}
__global__ void scan2_kernel(int nblk) {
    if (threadIdx.x == 0) {
        int run = 0;
        for (int b = 0; b < nblk; b++) { int t = g_blksum[b]; g_blkoff[b] = run; run += t; }
        g_rowptr[N_NODES] = run;
    }
}
__global__ void scan3_kernel() {
    int idx = blockIdx.x * 1024 + threadIdx.x;
    if (idx < N_NODES) g_rowptr[idx] += g_blkoff[blockIdx.x];
}
__global__ void scatter_kernel(const int* __restrict__ ei) {
    int e = blockIdx.x * blockDim.x + threadIdx.x;
    if (e < N_EDGES) {
        int d = ei[N_EDGES + e];
        int s = ei[e];
        int pos = atomicAdd(&g_cursor[d], 1);
        int slot = g_rowptr[d] + pos;
        g_csr[slot] = s;
        g_csrw[slot] = g_dis[s];
    }
}

// ---------------- mma.sync bf16 GEMM: C[M,N] = A[M,K] @ W[K,N] (W^T planes given) ----------------
// fp32 emulation: C = Ah*Bh + Al*Bh + Ah*Bl. BM=128, BN template, BK=32.
// 8 warps: 4 in M x 2 in N. cp.async double-buffered; ldmatrix.x4 fragments.
// MMA sweeps ordered so each accumulator's dependent MMAs are 16 ops apart.
__device__ __forceinline__ void cp_async16(uint32_t dst, const void* src, int szr) {
    asm volatile("cp.async.ca.shared.global [%0], [%1], 16, %2;"
                 :: "r"(dst), "l"(src), "r"(szr));
}
__device__ __forceinline__ void mma16816(float* c, const uint32_t* a, const uint32_t* b) {
    asm volatile(
        "mma.sync.aligned.m16n8k16.row.col.f32.bf16.bf16.f32 "
        "{%0,%1,%2,%3}, {%4,%5,%6,%7}, {%8,%9}, {%0,%1,%2,%3};"
        : "+f"(c[0]), "+f"(c[1]), "+f"(c[2]), "+f"(c[3])
        : "r"(a[0]), "r"(a[1]), "r"(a[2]), "r"(a[3]), "r"(b[0]), "r"(b[1]));
}
__device__ __forceinline__ void ldsm_x4(uint32_t* r, uint32_t addr) {
    asm volatile("ldmatrix.sync.aligned.m8n8.x4.shared.b16 {%0,%1,%2,%3}, [%4];"
        : "=r"(r[0]), "=r"(r[1]), "=r"(r[2]), "=r"(r[3]) : "r"(addr));
}

template<int BN>
__global__ void __launch_bounds__(256, 2)
mma_gemm_kernel(const __nv_bfloat16* __restrict__ Ahi, const __nv_bfloat16* __restrict__ Alo,
                const __nv_bfloat16* __restrict__ Bhi, const __nv_bfloat16* __restrict__ Blo,
                float* __restrict__ C, int M, int N, int K) {
    extern __shared__ char smem[];
    const int BSZ = BN * 80;
    const int BUF = 20480 + 2 * BSZ;
    const int NT = BN / 16;
    uint32_t sbase;
    asm("{ .reg .u64 t; cvta.to.shared.u64 t, %1; cvt.u32.u64 %0, t; }"
        : "=r"(sbase) : "l"(smem));

    int tid = threadIdx.x, lane = tid & 31, wid = tid >> 5;
    int gID = lane >> 2, tig = lane & 3;
    int warpM = (wid & 3) * 32, warpN = (wid >> 2) * (BN / 2);
    int bm = blockIdx.y * 128, bn = blockIdx.x * BN;

    uint32_t aOff = (uint32_t)((warpM + (lane & 7) + ((lane >> 3) & 1) * 8) * 80
                               + (lane >> 4) * 16);
    uint32_t b4Off = (uint32_t)((warpN + ((lane >> 4) << 3) + (lane & 7)) * 80
                                + ((lane >> 3) & 1) * 16);

    float acc[2][NT][4];
    #pragma unroll
    for (int i = 0; i < 2; i++)
        #pragma unroll
        for (int j = 0; j < NT; j++)
            #pragma unroll
            for (int q = 0; q < 4; q++) acc[i][j][q] = 0.f;

    int nch = K >> 5;

    auto load_tile = [&](int buf, int c) {
        uint32_t bb = sbase + buf * BUF;
        #pragma unroll
        for (int it = 0; it < 4; it++) {
            int idx = tid + it * 256;
            int ch = idx & 3, r = (idx >> 2) & 127, pl = idx >> 9;
            int row = bm + r;
            int szr = (row < M) ? 16 : 0;
            int rowc = (row < M) ? row : (M - 1);
            const __nv_bfloat16* src = (pl ? Alo : Ahi) + (size_t)rowc * K + c * 32 + ch * 8;
            cp_async16(bb + pl * 10240 + r * 80 + ch * 16, src, szr);
        }
        #pragma unroll
        for (int it = 0; it < BN / 32; it++) {
            int idx = tid + it * 256;
            int ch = idx & 3, r = (idx >> 2) % BN, pl = idx / (BN * 4);
            const __nv_bfloat16* src = (pl ? Blo : Bhi) + (size_t)(bn + r) * K + c * 32 + ch * 8;
            cp_async16(bb + 20480 + pl * BSZ + r * 80 + ch * 16, src, 16);
        }
    };

    load_tile(0, 0);
    asm volatile("cp.async.commit_group;");

    for (int c = 0; c < nch; c++) {
        if (c + 1 < nch) load_tile((c + 1) & 1, c + 1);
        asm volatile("cp.async.commit_group;");
        asm volatile("cp.async.wait_group 1;");
        __syncthreads();

        uint32_t bufb = sbase + (c & 1) * BUF;
        uint32_t aHi = bufb + aOff;
        uint32_t aLo = aHi + 10240;
        uint32_t bHi = bufb + 20480 + b4Off;
        uint32_t bLo = bHi + BSZ;

        #pragma unroll
        for (int ks = 0; ks < 2; ks++) {
            uint32_t ah[2][4], al[2][4], bb2[NT][2];
            #pragma unroll
            for (int mt = 0; mt < 2; mt++) {
                ldsm_x4(ah[mt], aHi + mt * (16 * 80) + ks * 32);
                ldsm_x4(al[mt], aLo + mt * (16 * 80) + ks * 32);
            }
            // B hi plane: sweep 1 (ah*bh, 16 independent), sweep 2 (al*bh)
            #pragma unroll
            for (int p = 0; p < NT / 2; p++)
                ldsm_x4(&bb2[2 * p][0], bHi + p * (16 * 80) + ks * 32);
            #pragma unroll
            for (int mt = 0; mt < 2; mt++)
                #pragma unroll
                for (int nt = 0; nt < NT; nt++)
                    mma16816(acc[mt][nt], ah[mt], bb2[nt]);
            #pragma unroll
            for (int mt = 0; mt < 2; mt++)
                #pragma unroll
                for (int nt = 0; nt < NT; nt++)
                    mma16816(acc[mt][nt], al[mt], bb2[nt]);
            // B lo plane: sweep 3 (ah*bl), bb2 registers reused
            #pragma unroll
            for (int p = 0; p < NT / 2; p++)
                ldsm_x4(&bb2[2 * p][0], bLo + p * (16 * 80) + ks * 32);
            #pragma unroll
            for (int mt = 0; mt < 2; mt++)
                #pragma unroll
                for (int nt = 0; nt < NT; nt++)
                    mma16816(acc[mt][nt], ah[mt], bb2[nt]);
        }
        __syncthreads();
    }

    #pragma unroll
    for (int mt = 0; mt < 2; mt++) {
        int row0 = bm + warpM + mt * 16 + gID;
        #pragma unroll
        for (int nt = 0; nt < NT; nt++) {
            int col = bn + warpN + nt * 8 + tig * 2;
            if (row0 < M)
                *(float2*)(C + (size_t)row0 * N + col) = make_float2(acc[mt][nt][0], acc[mt][nt][1]);
            if (row0 + 8 < M)
                *(float2*)(C + (size_t)(row0 + 8) * N + col) = make_float2(acc[mt][nt][2], acc[mt][nt][3]);
        }
    }
}

// ---------------- aggregation: float4 gather, 4 nodes per 256-thread block ----------------
__global__ void __launch_bounds__(256)
agg_pack_kernel(const float* __restrict__ h,
                const float* __restrict__ bias,
                __nv_bfloat16* __restrict__ ohi,
                __nv_bfloat16* __restrict__ olo) {
    __shared__ int   sE[4][64];
    __shared__ float sW[4][64];
    int g = threadIdx.x >> 6;
    int t = threadIdx.x & 63;
    int node = blockIdx.x * 4 + g;
    bool valid = node < N_NODES;

    int beg = 0, end = 0;
    if (valid) { beg = g_rowptr[node]; end = g_rowptr[node + 1]; }
    float4 acc = make_float4(0.f, 0.f, 0.f, 0.f);

    for (int cs = beg; cs < end; cs += 64) {
        int cnt = min(64, end - cs);
        if (t < cnt) { sE[g][t] = g_csr[cs + t]; sW[g][t] = g_csrw[cs + t]; }
        __syncthreads();
        #pragma unroll 2
        for (int i = 0; i < cnt; i++) {
            float w = sW[g][i];
            float4 v = __ldg((const float4*)(h + (size_t)sE[g][i] * F_H + t * 4));
            acc.x = fmaf(w, v.x, acc.x); acc.y = fmaf(w, v.y, acc.y);
            acc.z = fmaf(w, v.z, acc.z); acc.w = fmaf(w, v.w, acc.w);
        }
        __syncthreads();
    }
    if (valid) {
        float dn = g_dis[node];
        float4 hv = *(const float4*)(h + (size_t)node * F_H + t * 4);
        const float4 bv = *(const float4*)(bias + t * 4);
        float r[4] = {
            dn * fmaf(dn, hv.x, acc.x) + bv.x,
            dn * fmaf(dn, hv.y, acc.y) + bv.y,
            dn * fmaf(dn, hv.z, acc.z) + bv.z,
            dn * fmaf(dn, hv.w, acc.w) + bv.w };
        __nv_bfloat16 hi[4], lo[4];
        #pragma unroll
        for (int q = 0; q < 4; q++) {
            float v = r[q] > 0.f ? r[q] : 0.01f * r[q];
            split_bf16(v, hi[q], lo[q]);
        }
        __nv_bfloat162 hh0 = __halves2bfloat162(hi[0], hi[1]);
        __nv_bfloat162 hh1 = __halves2bfloat162(hi[2], hi[3]);
        __nv_bfloat162 ll0 = __halves2bfloat162(lo[0], lo[1]);
        __nv_bfloat162 ll1 = __halves2bfloat162(lo[2], lo[3]);
        *(uint2*)(ohi + (size_t)node * F_H + t * 4) = make_uint2(*(uint32_t*)&hh0, *(uint32_t*)&hh1);
        *(uint2*)(olo + (size_t)node * F_H + t * 4) = make_uint2(*(uint32_t*)&ll0, *(uint32_t*)&ll1);
    }
}

// last layer: agg (F=64) + bias + softmax. 16 threads x float4 per node, 16 nodes per block.
__global__ void __launch_bounds__(256)
agg_softmax_kernel(const float* __restrict__ h,
                   const float* __restrict__ bias,
                   float* __restrict__ out) {
    int g = threadIdx.x >> 4;
    int t = threadIdx.x & 15;
    int node = blockIdx.x * 16 + g;
    bool valid = node < N_NODES;

    float4 acc = make_float4(0.f, 0.f, 0.f, 0.f);
    if (valid) {
        int beg = g_rowptr[node], end = g_rowptr[node + 1];
        for (int e = beg; e < end; e++) {
            float w = g_csrw[e];
            float4 v = __ldg((const float4*)(h + (size_t)g_csr[e] * 64 + t * 4));
            acc.x = fmaf(w, v.x, acc.x); acc.y = fmaf(w, v.y, acc.y);
            acc.z = fmaf(w, v.z, acc.z); acc.w = fmaf(w, v.w, acc.w);
        }
        float dn = g_dis[node];
        float4 hv = *(const float4*)(h + (size_t)node * 64 + t * 4);
        const float4 bv = *(const float4*)(bias + t * 4);
        acc.x = dn * fmaf(dn, hv.x, acc.x) + bv.x;
        acc.y = dn * fmaf(dn, hv.y, acc.y) + bv.y;
        acc.z = dn * fmaf(dn, hv.z, acc.z) + bv.z;
        acc.w = dn * fmaf(dn, hv.w, acc.w) + bv.w;
    }
    float m = fmaxf(fmaxf(acc.x, acc.y), fmaxf(acc.z, acc.w));
    #pragma unroll
    for (int off = 8; off > 0; off >>= 1)
        m = fmaxf(m, __shfl_xor_sync(0xffffffffu, m, off, 16));
    float ex = expf(acc.x - m), ey = expf(acc.y - m);
    float ez = expf(acc.z - m), ew = expf(acc.w - m);
    float s = ex + ey + ez + ew;
    #pragma unroll
    for (int off = 8; off > 0; off >>= 1)
        s += __shfl_xor_sync(0xffffffffu, s, off, 16);
    if (valid) {
        float inv = 1.f / s;
        *(float4*)(out + (size_t)node * 64 + t * 4) = make_float4(ex * inv, ey * inv, ez * inv, ew * inv);
    }
}

// ---------------- launch ----------------
extern "C" void kernel_launch(void* const* d_in, const int* in_sizes, int n_in,
                              void* d_out, int out_size) {
    const float* x  = (const float*)d_in[0];
    const int*   ei = (const int*)  d_in[1];
    const float* W0 = (const float*)d_in[2];
    const float* b0 = (const float*)d_in[3];
    const float* W1 = (const float*)d_in[4];
    const float* b1 = (const float*)d_in[5];
    const float* W2 = (const float*)d_in[6];
    const float* b2 = (const float*)d_in[7];
    const float* W3 = (const float*)d_in[8];
    const float* b3 = (const float*)d_in[9];
    float* out = (float*)d_out;

    __nv_bfloat16 *ahi, *alo, *whibase, *wlobase;
    float* gout;
    cudaGetSymbolAddress((void**)&ahi, g_ahi);
    cudaGetSymbolAddress((void**)&alo, g_alo);
    cudaGetSymbolAddress((void**)&whibase, g_whi);
    cudaGetSymbolAddress((void**)&wlobase, g_wlo);
    cudaGetSymbolAddress((void**)&gout, g_gout);
    const size_t WSTRIDE = (size_t)F_IN * F_H;

    const int SM128 = 20480 + 2 * 128 * 80;          // per buffer
    const int SM64  = 20480 + 2 * 64 * 80;
    cudaFuncSetAttribute(mma_gemm_kernel<128>, cudaFuncAttributeMaxDynamicSharedMemorySize, 2 * SM128);
    cudaFuncSetAttribute(mma_gemm_kernel<64>,  cudaFuncAttributeMaxDynamicSharedMemorySize, 2 * SM64);

    // capture-safe fork/join resources (created once; reused every call)
    static cudaStream_t s2 = []{
        cudaStream_t s; cudaStreamCreateWithFlags(&s, cudaStreamNonBlocking); return s; }();
    static cudaEvent_t evFork = []{
        cudaEvent_t e; cudaEventCreateWithFlags(&e, cudaEventDisableTiming); return e; }();
    static cudaEvent_t evJoin = []{
        cudaEvent_t e; cudaEventCreateWithFlags(&e, cudaEventDisableTiming); return e; }();

    const int TB = 256;
    int nblk_nodes = (N_NODES + TB - 1) / TB;
    int nblk_edges = (N_EDGES + TB - 1) / TB;
    int scan_blks = (N_NODES + 1023) / 1024;
    int mtiles = (N_NODES + 127) / 128;

    // fork: CSR build on s2, concurrent with packing + gemm0 on main stream
    cudaEventRecord(evFork, 0);
    cudaStreamWaitEvent(s2, evFork, 0);

    zero_kernel<<<nblk_nodes, TB, 0, s2>>>();
    count_kernel<<<nblk_edges, TB, 0, s2>>>(ei);
    dis_kernel<<<nblk_nodes, TB, 0, s2>>>();
    scan1_kernel<<<scan_blks, 1024, 0, s2>>>();
    scan2_kernel<<<1, 32, 0, s2>>>(scan_blks);
    scan3_kernel<<<scan_blks, 1024, 0, s2>>>();
    scatter_kernel<<<nblk_edges, TB, 0, s2>>>(ei);
    cudaEventRecord(evJoin, s2);

    // main stream: packs + gemm0
    pack_x_kernel<<<(N_NODES * F_IN / 4 + TB - 1) / TB, TB>>>(x, ahi, alo, N_NODES * F_IN / 4);
    pack_w_kernel<<<(F_IN * F_H + TB - 1) / TB, TB>>>(W0, whibase, wlobase, F_IN, F_H);
    pack_w_kernel<<<(F_H * F_H + TB - 1) / TB, TB>>>(W1, whibase + WSTRIDE, wlobase + WSTRIDE, F_H, F_H);
    mma_gemm_kernel<128><<<dim3(2, mtiles), TB, 2 * SM128>>>(ahi, alo, whibase, wlobase, gout,
                                                             N_NODES, F_H, F_IN);
    pack_w_kernel<<<(F_H * F_H + TB - 1) / TB, TB>>>(W2, whibase + 2 * WSTRIDE, wlobase + 2 * WSTRIDE, F_H, F_H);
    pack_w_kernel<<<(F_H * F_OUT + TB - 1) / TB, TB>>>(W3, whibase + 3 * WSTRIDE, wlobase + 3 * WSTRIDE, F_H, F_OUT);

    // join: aggregation needs the CSR
    cudaStreamWaitEvent(0, evJoin, 0);

    agg_pack_kernel<<<(N_NODES + 3) / 4, TB>>>(gout, b0, ahi, alo);
    // Layer 1
    mma_gemm_kernel<128><<<dim3(2, mtiles), TB, 2 * SM128>>>(ahi, alo, whibase + WSTRIDE, wlobase + WSTRIDE,
                                                             gout, N_NODES, F_H, F_H);
    agg_pack_kernel<<<(N_NODES + 3) / 4, TB>>>(gout, b1, ahi, alo);
    // Layer 2
    mma_gemm_kernel<128><<<dim3(2, mtiles), TB, 2 * SM128>>>(ahi, alo, whibase + 2 * WSTRIDE, wlobase + 2 * WSTRIDE,
                                                             gout, N_NODES, F_H, F_H);
    agg_pack_kernel<<<(N_NODES + 3) / 4, TB>>>(gout, b2, ahi, alo);
    // Layer 3: 256 -> 64 + softmax
    mma_gemm_kernel<64><<<dim3(1, mtiles), TB, 2 * SM64>>>(ahi, alo, whibase + 3 * WSTRIDE, wlobase + 3 * WSTRIDE,
                                                           gout, N_NODES, F_OUT, F_H);
    agg_softmax_kernel<<<(N_NODES + 15) / 16, TB>>>(gout, b3, out);
}

// round 11
// speedup vs baseline: 1.1963x; 1.1350x over previous
#include <cuda_runtime.h>
#include <cuda_bf16.h>
#include <math.h>
#include <cstdint>

#define N_NODES 100000
#define N_EDGES 3200000
#define F_IN    512
#define F_H     256
#define F_OUT   64

// ---------------- scratch (device globals: no alloc allowed) ----------------
__device__ int   g_deg[N_NODES];
__device__ int   g_cursor[N_NODES];
__device__ int   g_rowptr[N_NODES + 1];
__device__ float g_dis[N_NODES];
__device__ int   g_csr[N_EDGES];
__device__ float g_csrw[N_EDGES];       // per-edge weight dis[src]
__device__ int   g_blksum[128];
__device__ int   g_blkoff[128];
__device__ __nv_bfloat16 g_ahi[(size_t)N_NODES * F_IN];   // activation hi plane
__device__ __nv_bfloat16 g_alo[(size_t)N_NODES * F_IN];   // activation lo plane
__device__ float g_gout[(size_t)N_NODES * F_H];           // GEMM output (pre-agg) fp32
__device__ __nv_bfloat16 g_whi[4][(size_t)F_IN * F_H];    // W^T hi plane [N][K]
__device__ __nv_bfloat16 g_wlo[4][(size_t)F_IN * F_H];    // W^T lo plane [N][K]

// ---------------- packing helpers ----------------
__device__ __forceinline__ void split_bf16(float v, __nv_bfloat16& hi, __nv_bfloat16& lo) {
    hi = __float2bfloat16(v);
    lo = __float2bfloat16(v - __bfloat162float(hi));
}

__global__ void pack_x_kernel(const float* __restrict__ x,
                              __nv_bfloat16* __restrict__ hi,
                              __nv_bfloat16* __restrict__ lo, int n4) {
    int i = blockIdx.x * blockDim.x + threadIdx.x;
    if (i < n4) {
        float4 v = *(const float4*)(x + (size_t)i * 4);
        __nv_bfloat16 h0, l0, h1, l1, h2, l2, h3, l3;
        split_bf16(v.x, h0, l0); split_bf16(v.y, h1, l1);
        split_bf16(v.z, h2, l2); split_bf16(v.w, h3, l3);
        __nv_bfloat162 hh0 = __halves2bfloat162(h0, h1);
        __nv_bfloat162 hh1 = __halves2bfloat162(h2, h3);
        __nv_bfloat162 ll0 = __halves2bfloat162(l0, l1);
        __nv_bfloat162 ll1 = __halves2bfloat162(l2, l3);
        *(uint2*)(hi + (size_t)i * 4) = make_uint2(*(uint32_t*)&hh0, *(uint32_t*)&hh1);
        *(uint2*)(lo + (size_t)i * 4) = make_uint2(*(uint32_t*)&ll0, *(uint32_t*)&ll1);
    }
}

// W [K,N] fp32 -> W^T planes [N][K]
__global__ void pack_w_kernel(const float* __restrict__ W,
                              __nv_bfloat16* __restrict__ hi,
                              __nv_bfloat16* __restrict__ lo, int K, int N) {
    int i = blockIdx.x * blockDim.x + threadIdx.x;
    if (i < K * N) {
        int k = i / N, n = i % N;
        __nv_bfloat16 h, l;
        split_bf16(W[i], h, l);
        hi[(size_t)n * K + k] = h;
        lo[(size_t)n * K + k] = l;
    }
}

// ---------------- CSR build ----------------
__global__ void zero_kernel() {
    int i = blockIdx.x * blockDim.x + threadIdx.x;
    if (i < N_NODES) { g_deg[i] = 0; g_cursor[i] = 0; }
}
__global__ void count_kernel(const int* __restrict__ ei) {
    int e = blockIdx.x * blockDim.x + threadIdx.x;
    if (e < N_EDGES) atomicAdd(&g_deg[ei[N_EDGES + e]], 1);
}
__global__ void dis_kernel() {
    int n = blockIdx.x * blockDim.x + threadIdx.x;
    if (n < N_NODES) g_dis[n] = rsqrtf((float)g_deg[n] + 1.0f);
}
__global__ void scan1_kernel() {
    __shared__ int sh[1024];
    int tid = threadIdx.x;
    int idx = blockIdx.x * 1024 + tid;
    int v = (idx < N_NODES) ? g_deg[idx] : 0;
    sh[tid] = v;
    __syncthreads();
    #pragma unroll
    for (int off = 1; off < 1024; off <<= 1) {
        int t = (tid >= off) ? sh[tid - off] : 0;
        __syncthreads();
        sh[tid] += t;
        __syncthreads();
    }
    if (idx < N_NODES) g_rowptr[idx] = sh[tid] - v;
    if (tid == 1023) g_blksum[blockIdx.x] = sh[1023];
}
__global__ void scan2_kernel(int nblk) {
    if (threadIdx.x == 0) {
        int run = 0;
        for (int b = 0; b < nblk; b++) { int t = g_blksum[b]; g_blkoff[b] = run; run += t; }
        g_rowptr[N_NODES] = run;
    }
}
__global__ void scan3_kernel() {
    int idx = blockIdx.x * 1024 + threadIdx.x;
    if (idx < N_NODES) g_rowptr[idx] += g_blkoff[blockIdx.x];
}
__global__ void scatter_kernel(const int* __restrict__ ei) {
    int e = blockIdx.x * blockDim.x + threadIdx.x;
    if (e < N_EDGES) {
        int d = ei[N_EDGES + e];
        int s = ei[e];
        int pos = atomicAdd(&g_cursor[d], 1);
        int slot = g_rowptr[d] + pos;
        g_csr[slot] = s;
        g_csrw[slot] = g_dis[s];
    }
}

// ---------------- mma.sync bf16 GEMM: C[M,N] = A[M,K] @ W[K,N] (W^T planes given) ----------------
__device__ __forceinline__ void cp_async16(uint32_t dst, const void* src, int szr) {
    asm volatile("cp.async.ca.shared.global [%0], [%1], 16, %2;"
                 :: "r"(dst), "l"(src), "r"(szr));
}
__device__ __forceinline__ void mma16816(float* c, const uint32_t* a, const uint32_t* b) {
    asm volatile(
        "mma.sync.aligned.m16n8k16.row.col.f32.bf16.bf16.f32 "
        "{%0,%1,%2,%3}, {%4,%5,%6,%7}, {%8,%9}, {%0,%1,%2,%3};"
        : "+f"(c[0]), "+f"(c[1]), "+f"(c[2]), "+f"(c[3])
        : "r"(a[0]), "r"(a[1]), "r"(a[2]), "r"(a[3]), "r"(b[0]), "r"(b[1]));
}
__device__ __forceinline__ void ldsm_x4(uint32_t* r, uint32_t addr) {
    asm volatile("ldmatrix.sync.aligned.m8n8.x4.shared.b16 {%0,%1,%2,%3}, [%4];"
        : "=r"(r[0]), "=r"(r[1]), "=r"(r[2]), "=r"(r[3]) : "r"(addr));
}

template<int BN>
__global__ void __launch_bounds__(256, 2)
mma_gemm_kernel(const __nv_bfloat16* __restrict__ Ahi, const __nv_bfloat16* __restrict__ Alo,
                const __nv_bfloat16* __restrict__ Bhi, const __nv_bfloat16* __restrict__ Blo,
                float* __restrict__ C, int M, int N, int K) {
    extern __shared__ char smem[];
    const int BSZ = BN * 80;
    const int BUF = 20480 + 2 * BSZ;
    const int NT = BN / 16;
    uint32_t sbase;
    asm("{ .reg .u64 t; cvta.to.shared.u64 t, %1; cvt.u32.u64 %0, t; }"
        : "=r"(sbase) : "l"(smem));

    int tid = threadIdx.x, lane = tid & 31, wid = tid >> 5;
    int gID = lane >> 2, tig = lane & 3;
    int warpM = (wid & 3) * 32, warpN = (wid >> 2) * (BN / 2);
    int bm = blockIdx.y * 128, bn = blockIdx.x * BN;

    uint32_t aOff = (uint32_t)((warpM + (lane & 7) + ((lane >> 3) & 1) * 8) * 80
                               + (lane >> 4) * 16);
    uint32_t b4Off = (uint32_t)((warpN + ((lane >> 4) << 3) + (lane & 7)) * 80
                                + ((lane >> 3) & 1) * 16);

    float acc[2][NT][4];
    #pragma unroll
    for (int i = 0; i < 2; i++)
        #pragma unroll
        for (int j = 0; j < NT; j++)
            #pragma unroll
            for (int q = 0; q < 4; q++) acc[i][j][q] = 0.f;

    int nch = K >> 5;

    auto load_tile = [&](int buf, int c) {
        uint32_t bb = sbase + buf * BUF;
        #pragma unroll
        for (int it = 0; it < 4; it++) {
            int idx = tid + it * 256;
            int ch = idx & 3, r = (idx >> 2) & 127, pl = idx >> 9;
            int row = bm + r;
            int szr = (row < M) ? 16 : 0;
            int rowc = (row < M) ? row : (M - 1);
            const __nv_bfloat16* src = (pl ? Alo : Ahi) + (size_t)rowc * K + c * 32 + ch * 8;
            cp_async16(bb + pl * 10240 + r * 80 + ch * 16, src, szr);
        }
        #pragma unroll
        for (int it = 0; it < BN / 32; it++) {
            int idx = tid + it * 256;
            int ch = idx & 3, r = (idx >> 2) % BN, pl = idx / (BN * 4);
            const __nv_bfloat16* src = (pl ? Blo : Bhi) + (size_t)(bn + r) * K + c * 32 + ch * 8;
            cp_async16(bb + 20480 + pl * BSZ + r * 80 + ch * 16, src, 16);
        }
    };

    load_tile(0, 0);
    asm volatile("cp.async.commit_group;");

    for (int c = 0; c < nch; c++) {
        if (c + 1 < nch) load_tile((c + 1) & 1, c + 1);
        asm volatile("cp.async.commit_group;");
        asm volatile("cp.async.wait_group 1;");
        __syncthreads();

        uint32_t bufb = sbase + (c & 1) * BUF;
        uint32_t aHi = bufb + aOff;
        uint32_t aLo = aHi + 10240;
        uint32_t bHi = bufb + 20480 + b4Off;
        uint32_t bLo = bHi + BSZ;

        #pragma unroll
        for (int ks = 0; ks < 2; ks++) {
            uint32_t ah[2][4], al[2][4], bb2[NT][2];
            #pragma unroll
            for (int mt = 0; mt < 2; mt++) {
                ldsm_x4(ah[mt], aHi + mt * (16 * 80) + ks * 32);
                ldsm_x4(al[mt], aLo + mt * (16 * 80) + ks * 32);
            }
            #pragma unroll
            for (int p = 0; p < NT / 2; p++)
                ldsm_x4(&bb2[2 * p][0], bHi + p * (16 * 80) + ks * 32);
            #pragma unroll
            for (int mt = 0; mt < 2; mt++)
                #pragma unroll
                for (int nt = 0; nt < NT; nt++)
                    mma16816(acc[mt][nt], ah[mt], bb2[nt]);
            #pragma unroll
            for (int mt = 0; mt < 2; mt++)
                #pragma unroll
                for (int nt = 0; nt < NT; nt++)
                    mma16816(acc[mt][nt], al[mt], bb2[nt]);
            #pragma unroll
            for (int p = 0; p < NT / 2; p++)
                ldsm_x4(&bb2[2 * p][0], bLo + p * (16 * 80) + ks * 32);
            #pragma unroll
            for (int mt = 0; mt < 2; mt++)
                #pragma unroll
                for (int nt = 0; nt < NT; nt++)
                    mma16816(acc[mt][nt], ah[mt], bb2[nt]);
        }
        __syncthreads();
    }

    #pragma unroll
    for (int mt = 0; mt < 2; mt++) {
        int row0 = bm + warpM + mt * 16 + gID;
        #pragma unroll
        for (int nt = 0; nt < NT; nt++) {
            int col = bn + warpN + nt * 8 + tig * 2;
            if (row0 < M)
                *(float2*)(C + (size_t)row0 * N + col) = make_float2(acc[mt][nt][0], acc[mt][nt][1]);
            if (row0 + 8 < M)
                *(float2*)(C + (size_t)(row0 + 8) * N + col) = make_float2(acc[mt][nt][2], acc[mt][nt][3]);
        }
    }
}

// ---------------- aggregation: warp-per-node, no barriers ----------------
// lane handles features [lane*4, lane*4+4) and [128+lane*4, 128+lane*4+4)
__global__ void __launch_bounds__(256)
agg_pack_kernel(const float* __restrict__ h,
                const float* __restrict__ bias,
                __nv_bfloat16* __restrict__ ohi,
                __nv_bfloat16* __restrict__ olo) {
    int node = (blockIdx.x * blockDim.x + threadIdx.x) >> 5;
    int lane = threadIdx.x & 31;
    if (node >= N_NODES) return;

    int beg = g_rowptr[node], end = g_rowptr[node + 1];
    float4 a0 = make_float4(0.f, 0.f, 0.f, 0.f);
    float4 a1 = make_float4(0.f, 0.f, 0.f, 0.f);
    int f0 = lane * 4, f1 = 128 + lane * 4;

    int e = beg;
    for (; e + 2 <= end; e += 2) {
        int   s0 = __ldg(&g_csr[e]),  s1 = __ldg(&g_csr[e + 1]);
        float w0 = __ldg(&g_csrw[e]), w1 = __ldg(&g_csrw[e + 1]);
        float4 v00 = __ldg((const float4*)(h + (size_t)s0 * F_H + f0));
        float4 v01 = __ldg((const float4*)(h + (size_t)s0 * F_H + f1));
        float4 v10 = __ldg((const float4*)(h + (size_t)s1 * F_H + f0));
        float4 v11 = __ldg((const float4*)(h + (size_t)s1 * F_H + f1));
        a0.x = fmaf(w0, v00.x, fmaf(w1, v10.x, a0.x));
        a0.y = fmaf(w0, v00.y, fmaf(w1, v10.y, a0.y));
        a0.z = fmaf(w0, v00.z, fmaf(w1, v10.z, a0.z));
        a0.w = fmaf(w0, v00.w, fmaf(w1, v10.w, a0.w));
        a1.x = fmaf(w0, v01.x, fmaf(w1, v11.x, a1.x));
        a1.y = fmaf(w0, v01.y, fmaf(w1, v11.y, a1.y));
        a1.z = fmaf(w0, v01.z, fmaf(w1, v11.z, a1.z));
        a1.w = fmaf(w0, v01.w, fmaf(w1, v11.w, a1.w));
    }
    if (e < end) {
        int   s0 = __ldg(&g_csr[e]);
        float w0 = __ldg(&g_csrw[e]);
        float4 v00 = __ldg((const float4*)(h + (size_t)s0 * F_H + f0));
        float4 v01 = __ldg((const float4*)(h + (size_t)s0 * F_H + f1));
        a0.x = fmaf(w0, v00.x, a0.x); a0.y = fmaf(w0, v00.y, a0.y);
        a0.z = fmaf(w0, v00.z, a0.z); a0.w = fmaf(w0, v00.w, a0.w);
        a1.x = fmaf(w0, v01.x, a1.x); a1.y = fmaf(w0, v01.y, a1.y);
        a1.z = fmaf(w0, v01.z, a1.z); a1.w = fmaf(w0, v01.w, a1.w);
    }

    float dn = g_dis[node];
    float4 h0 = *(const float4*)(h + (size_t)node * F_H + f0);
    float4 h1 = *(const float4*)(h + (size_t)node * F_H + f1);
    float4 b0 = *(const float4*)(bias + f0);
    float4 b1 = *(const float4*)(bias + f1);
    float r0[4] = { dn * fmaf(dn, h0.x, a0.x) + b0.x,
                    dn * fmaf(dn, h0.y, a0.y) + b0.y,
                    dn * fmaf(dn, h0.z, a0.z) + b0.z,
                    dn * fmaf(dn, h0.w, a0.w) + b0.w };
    float r1[4] = { dn * fmaf(dn, h1.x, a1.x) + b1.x,
                    dn * fmaf(dn, h1.y, a1.y) + b1.y,
                    dn * fmaf(dn, h1.z, a1.z) + b1.z,
                    dn * fmaf(dn, h1.w, a1.w) + b1.w };

    __nv_bfloat16 hi[4], lo[4];
    #pragma unroll
    for (int q = 0; q < 4; q++) {
        float v = r0[q] > 0.f ? r0[q] : 0.01f * r0[q];
        split_bf16(v, hi[q], lo[q]);
    }
    __nv_bfloat162 p0 = __halves2bfloat162(hi[0], hi[1]);
    __nv_bfloat162 p1 = __halves2bfloat162(hi[2], hi[3]);
    __nv_bfloat162 q0 = __halves2bfloat162(lo[0], lo[1]);
    __nv_bfloat162 q1 = __halves2bfloat162(lo[2], lo[3]);
    *(uint2*)(ohi + (size_t)node * F_H + f0) = make_uint2(*(uint32_t*)&p0, *(uint32_t*)&p1);
    *(uint2*)(olo + (size_t)node * F_H + f0) = make_uint2(*(uint32_t*)&q0, *(uint32_t*)&q1);
    #pragma unroll
    for (int q = 0; q < 4; q++) {
        float v = r1[q] > 0.f ? r1[q] : 0.01f * r1[q];
        split_bf16(v, hi[q], lo[q]);
    }
    p0 = __halves2bfloat162(hi[0], hi[1]);
    p1 = __halves2bfloat162(hi[2], hi[3]);
    q0 = __halves2bfloat162(lo[0], lo[1]);
    q1 = __halves2bfloat162(lo[2], lo[3]);
    *(uint2*)(ohi + (size_t)node * F_H + f1) = make_uint2(*(uint32_t*)&p0, *(uint32_t*)&p1);
    *(uint2*)(olo + (size_t)node * F_H + f1) = make_uint2(*(uint32_t*)&q0, *(uint32_t*)&q1);
}

// last layer: agg (F=64) + bias + softmax. 16 threads x float4 per node, 16 nodes per block.
__global__ void __launch_bounds__(256)
agg_softmax_kernel(const float* __restrict__ h,
                   const float* __restrict__ bias,
                   float* __restrict__ out) {
    int g = threadIdx.x >> 4;
    int t = threadIdx.x & 15;
    int node = blockIdx.x * 16 + g;
    bool valid = node < N_NODES;

    float4 acc = make_float4(0.f, 0.f, 0.f, 0.f);
    if (valid) {
        int beg = g_rowptr[node], end = g_rowptr[node + 1];
        for (int e = beg; e < end; e++) {
            float w = g_csrw[e];
            float4 v = __ldg((const float4*)(h + (size_t)g_csr[e] * 64 + t * 4));
            acc.x = fmaf(w, v.x, acc.x); acc.y = fmaf(w, v.y, acc.y);
            acc.z = fmaf(w, v.z, acc.z); acc.w = fmaf(w, v.w, acc.w);
        }
        float dn = g_dis[node];
        float4 hv = *(const float4*)(h + (size_t)node * 64 + t * 4);
        const float4 bv = *(const float4*)(bias + t * 4);
        acc.x = dn * fmaf(dn, hv.x, acc.x) + bv.x;
        acc.y = dn * fmaf(dn, hv.y, acc.y) + bv.y;
        acc.z = dn * fmaf(dn, hv.z, acc.z) + bv.z;
        acc.w = dn * fmaf(dn, hv.w, acc.w) + bv.w;
    }
    float m = fmaxf(fmaxf(acc.x, acc.y), fmaxf(acc.z, acc.w));
    #pragma unroll
    for (int off = 8; off > 0; off >>= 1)
        m = fmaxf(m, __shfl_xor_sync(0xffffffffu, m, off, 16));
    float ex = expf(acc.x - m), ey = expf(acc.y - m);
    float ez = expf(acc.z - m), ew = expf(acc.w - m);
    float s = ex + ey + ez + ew;
    #pragma unroll
    for (int off = 8; off > 0; off >>= 1)
        s += __shfl_xor_sync(0xffffffffu, s, off, 16);
    if (valid) {
        float inv = 1.f / s;
        *(float4*)(out + (size_t)node * 64 + t * 4) = make_float4(ex * inv, ey * inv, ez * inv, ew * inv);
    }
}

// ---------------- launch ----------------
extern "C" void kernel_launch(void* const* d_in, const int* in_sizes, int n_in,
                              void* d_out, int out_size) {
    const float* x  = (const float*)d_in[0];
    const int*   ei = (const int*)  d_in[1];
    const float* W0 = (const float*)d_in[2];
    const float* b0 = (const float*)d_in[3];
    const float* W1 = (const float*)d_in[4];
    const float* b1 = (const float*)d_in[5];
    const float* W2 = (const float*)d_in[6];
    const float* b2 = (const float*)d_in[7];
    const float* W3 = (const float*)d_in[8];
    const float* b3 = (const float*)d_in[9];
    float* out = (float*)d_out;

    __nv_bfloat16 *ahi, *alo, *whibase, *wlobase;
    float* gout;
    cudaGetSymbolAddress((void**)&ahi, g_ahi);
    cudaGetSymbolAddress((void**)&alo, g_alo);
    cudaGetSymbolAddress((void**)&whibase, g_whi);
    cudaGetSymbolAddress((void**)&wlobase, g_wlo);
    cudaGetSymbolAddress((void**)&gout, g_gout);
    const size_t WSTRIDE = (size_t)F_IN * F_H;

    const int SM128 = 20480 + 2 * 128 * 80;          // per buffer
    const int SM64  = 20480 + 2 * 64 * 80;
    cudaFuncSetAttribute(mma_gemm_kernel<128>, cudaFuncAttributeMaxDynamicSharedMemorySize, 2 * SM128);
    cudaFuncSetAttribute(mma_gemm_kernel<64>,  cudaFuncAttributeMaxDynamicSharedMemorySize, 2 * SM64);

    // capture-safe fork/join resources (created once; reused every call)
    static cudaStream_t s2 = []{
        cudaStream_t s; cudaStreamCreateWithFlags(&s, cudaStreamNonBlocking); return s; }();
    static cudaEvent_t evFork = []{
        cudaEvent_t e; cudaEventCreateWithFlags(&e, cudaEventDisableTiming); return e; }();
    static cudaEvent_t evJoin = []{
        cudaEvent_t e; cudaEventCreateWithFlags(&e, cudaEventDisableTiming); return e; }();

    const int TB = 256;
    int nblk_nodes = (N_NODES + TB - 1) / TB;
    int nblk_edges = (N_EDGES + TB - 1) / TB;
    int scan_blks = (N_NODES + 1023) / 1024;
    int mtiles = (N_NODES + 127) / 128;
    int agg_blks = (N_NODES * 32 + TB - 1) / TB;     // warp-per-node

    // fork: CSR build on s2, concurrent with packing + gemm0 on main stream
    cudaEventRecord(evFork, 0);
    cudaStreamWaitEvent(s2, evFork, 0);

    zero_kernel<<<nblk_nodes, TB, 0, s2>>>();
    count_kernel<<<nblk_edges, TB, 0, s2>>>(ei);
    dis_kernel<<<nblk_nodes, TB, 0, s2>>>();
    scan1_kernel<<<scan_blks, 1024, 0, s2>>>();
    scan2_kernel<<<1, 32, 0, s2>>>(scan_blks);
    scan3_kernel<<<scan_blks, 1024, 0, s2>>>();
    scatter_kernel<<<nblk_edges, TB, 0, s2>>>(ei);
    cudaEventRecord(evJoin, s2);

    // main stream: packs + gemm0
    pack_x_kernel<<<(N_NODES * F_IN / 4 + TB - 1) / TB, TB>>>(x, ahi, alo, N_NODES * F_IN / 4);
    pack_w_kernel<<<(F_IN * F_H + TB - 1) / TB, TB>>>(W0, whibase, wlobase, F_IN, F_H);
    pack_w_kernel<<<(F_H * F_H + TB - 1) / TB, TB>>>(W1, whibase + WSTRIDE, wlobase + WSTRIDE, F_H, F_H);
    mma_gemm_kernel<128><<<dim3(2, mtiles), TB, 2 * SM128>>>(ahi, alo, whibase, wlobase, gout,
                                                             N_NODES, F_H, F_IN);
    pack_w_kernel<<<(F_H * F_H + TB - 1) / TB, TB>>>(W2, whibase + 2 * WSTRIDE, wlobase + 2 * WSTRIDE, F_H, F_H);
    pack_w_kernel<<<(F_H * F_OUT + TB - 1) / TB, TB>>>(W3, whibase + 3 * WSTRIDE, wlobase + 3 * WSTRIDE, F_H, F_OUT);

    // join: aggregation needs the CSR
    cudaStreamWaitEvent(0, evJoin, 0);

    agg_pack_kernel<<<agg_blks, TB>>>(gout, b0, ahi, alo);
    // Layer 1
    mma_gemm_kernel<128><<<dim3(2, mtiles), TB, 2 * SM128>>>(ahi, alo, whibase + WSTRIDE, wlobase + WSTRIDE,
                                                             gout, N_NODES, F_H, F_H);
    agg_pack_kernel<<<agg_blks, TB>>>(gout, b1, ahi, alo);
    // Layer 2
    mma_gemm_kernel<128><<<dim3(2, mtiles), TB, 2 * SM128>>>(ahi, alo, whibase + 2 * WSTRIDE, wlobase + 2 * WSTRIDE,
                                                             gout, N_NODES, F_H, F_H);
    agg_pack_kernel<<<agg_blks, TB>>>(gout, b2, ahi, alo);
    // Layer 3: 256 -> 64 + softmax
    mma_gemm_kernel<64><<<dim3(1, mtiles), TB, 2 * SM64>>>(ahi, alo, whibase + 3 * WSTRIDE, wlobase + 3 * WSTRIDE,
                                                           gout, N_NODES, F_OUT, F_H);
    agg_softmax_kernel<<<(N_NODES + 15) / 16, TB>>>(gout, b3, out);
}